// round 5
// baseline (speedup 1.0000x reference)
#include <cuda_runtime.h>
#include <math.h>

#define B_DIM 64
#define C_DIM 80
#define T_DIM 16384
#define NTHREADS 512
#define NWARPS 16
#define NBIN1 4096
#define CAP 4096
#define FULL 0xFFFFFFFFu
#define INVD 0xFFFFu   // sentinel digit for inactive lanes (> any real 12-bit digit)

// order-preserving float <-> u32 key (branch-free)
__device__ __forceinline__ unsigned f2k(float f) {
    unsigned u = __float_as_uint(f);
    return u ^ ((unsigned)((int)u >> 31) | 0x80000000u);
}
__device__ __forceinline__ float k2f(unsigned k) {
    unsigned m = (k & 0x80000000u) ? 0x80000000u : 0xFFFFFFFFu;
    return __uint_as_float(k ^ m);
}

__global__ void __launch_bounds__(NTHREADS, 3)
statpool_kernel(const float* __restrict__ x, const int* __restrict__ lengths,
                float* __restrict__ out) {
    extern __shared__ unsigned sh[];
    unsigned* hist1 = sh;                      // [4096]; reused as candidate list
    unsigned* hist2 = sh + NBIN1;              // [6*1024]; reused for level 3
    unsigned char* gmask = (unsigned char*)(hist2 + 6 * 1024);  // [4096]

    __shared__ float red_s[NWARPS], red_s2[NWARPS];
    __shared__ unsigned wtot[NWARPS], wbase[NWARPS];
    __shared__ unsigned s_k[6];
    __shared__ float s_w[3];
    __shared__ unsigned s_pfx12[6], s_krem[6];
    __shared__ int s_g12[6];
    __shared__ unsigned s_dig2[6], s_krem2[6], s_p22[6];
    __shared__ int s_g3[6], s_ng3;
    __shared__ unsigned s_upfx22[6];
    __shared__ unsigned s_keyout[6];
    __shared__ int s_cnt;

    const int row = blockIdx.x;
    const int b = row / C_DIM, c = row % C_DIM;
    const int n = lengths[b];
    const int tid = threadIdx.x, lane = tid & 31, warp = tid >> 5;

    for (int i = tid; i < NBIN1; i += NTHREADS) hist1[i] = 0u;
    if (tid == 0) s_cnt = 0;
    __syncthreads();

    // ---- pass 1: sum/sumsq + 12-bit histogram over VALID elements only.
    //      Uniform trip count; inactive lanes carry sentinel digit so
    //      __match_any_sync is always warp-converged. One atomic per
    //      distinct digit per warp (aggregated). ----
    const float4* x4 = (const float4*)(x + (size_t)row * T_DIM);
    const int nvec_full = n >> 2;                 // vectors with 4 valid elems
    const int iters1 = (nvec_full + NTHREADS - 1) / NTHREADS;
    float sum = 0.f, sumsq = 0.f;
    for (int it = 0; it < iters1; ++it) {
        const int i = tid + it * NTHREADS;
        const bool vld = i < nvec_full;
        float4 v = vld ? x4[i] : make_float4(0.f, 0.f, 0.f, 0.f);
        float vv[4] = {v.x, v.y, v.z, v.w};
#pragma unroll
        for (int j = 0; j < 4; ++j) {
            float f = vv[j];
            if (vld) { sum += f; sumsq += f * f; }
            unsigned digit = vld ? (f2k(f) >> 20) : INVD;
            unsigned peers = __match_any_sync(FULL, digit);
            if (digit != INVD && lane == (unsigned)(__ffs(peers) - 1))
                atomicAdd(&hist1[digit], (unsigned)__popc(peers));
        }
    }
    // scalar tail (n % 4 leftover elements), single thread, no collectives
    if (tid == 0) {
        const float* xs = (const float*)x4;
        for (int t = nvec_full << 2; t < n; ++t) {
            float f = xs[t];
            sum += f; sumsq += f * f;
            atomicAdd(&hist1[f2k(f) >> 20], 1u);
        }
    }

    // ---- block reduce sums (uniform control flow) ----
#pragma unroll
    for (int o = 16; o; o >>= 1) {
        sum += __shfl_down_sync(FULL, sum, o);
        sumsq += __shfl_down_sync(FULL, sumsq, o);
    }
    if (lane == 0) { red_s[warp] = sum; red_s2[warp] = sumsq; }
    __syncthreads();

    // ---- scan hist1 (inclusive, in place): thread owns 8 consecutive bins ----
    unsigned vbin[8], loc = 0;
#pragma unroll
    for (int d = 0; d < 8; ++d) { vbin[d] = hist1[tid * 8 + d]; loc += vbin[d]; }
    unsigned inc = loc;
#pragma unroll
    for (int o = 1; o < 32; o <<= 1) {
        unsigned t = __shfl_up_sync(FULL, inc, o);
        if (lane >= o) inc += t;
    }
    if (lane == 31) wtot[warp] = inc;
    __syncthreads();

    if (warp == 0) {
        unsigned t = (lane < NWARPS) ? wtot[lane] : 0u;
        unsigned ti = t;
#pragma unroll
        for (int o = 1; o < 16; o <<= 1) {
            unsigned u = __shfl_up_sync(FULL, ti, o);
            if (lane >= o) ti += u;
        }
        if (lane < NWARPS) wbase[lane] = ti - t;
    } else if (tid == 32) {
        // mean/std + rank targets (concurrent with warp 0's base scan)
        float s = 0.f, s2 = 0.f;
#pragma unroll
        for (int w = 0; w < NWARPS; ++w) { s += red_s[w]; s2 += red_s2[w]; }
        float fn = (float)n;
        float mean = s / fn;
        float var = fmaxf(s2 / fn - mean * mean, 1e-6f);
        out[b * (5 * C_DIM) + 0 * C_DIM + c] = mean;
        out[b * (5 * C_DIM) + 1 * C_DIM + c] = sqrtf(var);
        float n1 = (float)(n - 1);
        const float qs[3] = {0.25f, 0.5f, 0.75f};
#pragma unroll
        for (int q = 0; q < 3; ++q) {
            float pos = qs[q] * n1;
            float flo = floorf(pos);
            s_k[2 * q]     = (unsigned)(int)flo;
            s_k[2 * q + 1] = (unsigned)(int)ceilf(pos);
            s_w[q] = pos - flo;
        }
    }
    __syncthreads();

    unsigned run = wbase[warp] + (inc - loc);
#pragma unroll
    for (int d = 0; d < 8; ++d) { run += vbin[d]; hist1[tid * 8 + d] = run; }
    __syncthreads();

    // ---- resolve 12-bit prefix per target (6 threads binary search);
    //      others zero gmask + hist2 concurrently ----
    if (tid < 6) {
        unsigned k = s_k[tid];
        int lo = 0, hi = NBIN1 - 1;
        while (lo < hi) {
            int mid = (lo + hi) >> 1;
            if (hist1[mid] > k) hi = mid; else lo = mid + 1;
        }
        s_pfx12[tid] = (unsigned)lo;
        s_krem[tid] = k - (lo ? hist1[lo - 1] : 0u);
    }
    {
        unsigned* gm32 = (unsigned*)gmask;
        for (int i = tid; i < 1024; i += NTHREADS) gm32[i] = 0u;
        for (int i = tid; i < 6 * 1024; i += NTHREADS) hist2[i] = 0u;
    }
    __syncthreads();

    // ---- dedup 12-bit groups, fill gmask ----
    if (tid == 0) {
        int ng = 0;
        unsigned upfx[6];
#pragma unroll
        for (int j = 0; j < 6; ++j) {
            unsigned p = s_pfx12[j];
            int g = -1;
            for (int g2 = 0; g2 < ng; ++g2) if (upfx[g2] == p) { g = g2; break; }
            if (g < 0) { g = ng; upfx[ng++] = p; gmask[p] = (unsigned char)(g + 1); }
            s_g12[j] = g;
        }
    }
    __syncthreads();

    // ---- compaction: re-read row (L2-hot), append candidates.
    //      Uniform trip count, converged warp scans. ----
    unsigned* list = hist1;  // overlay (cumsums no longer needed)
    for (int it = 0; it < iters1; ++it) {
        const int i = tid + it * NTHREADS;
        const bool vld = i < nvec_full;
        float4 v = vld ? x4[i] : make_float4(0.f, 0.f, 0.f, 0.f);
        float vv[4] = {v.x, v.y, v.z, v.w};
        unsigned kk[4]; int gg[4]; int cl = 0;
#pragma unroll
        for (int j = 0; j < 4; ++j) {
            kk[j] = f2k(vv[j]);
            gg[j] = vld ? (int)gmask[kk[j] >> 20] : 0;
            cl += (gg[j] ? 1 : 0);
        }
        int incl = cl;
#pragma unroll
        for (int o = 1; o < 32; o <<= 1) {
            int t = __shfl_up_sync(FULL, incl, o);
            if (lane >= o) incl += t;
        }
        int wsum = __shfl_sync(FULL, incl, 31);
        int base = 0;
        if (lane == 31 && wsum) base = atomicAdd(&s_cnt, wsum);
        base = __shfl_sync(FULL, base, 31);
        int pos = base + incl - cl;
#pragma unroll
        for (int j = 0; j < 4; ++j) {
            if (gg[j]) { if (pos < CAP) list[pos] = kk[j]; pos++; }
        }
    }
    // scalar tail appends
    if (tid == 0) {
        const float* xs = (const float*)x4;
        for (int t = nvec_full << 2; t < n; ++t) {
            unsigned key = f2k(xs[t]);
            if (gmask[key >> 20]) {
                int pos = atomicAdd(&s_cnt, 1);
                if (pos < CAP) list[pos] = key;
            }
        }
    }
    __syncthreads();

    const int cnt = s_cnt;
    const bool ovf = cnt > CAP;  // adversarial-data fallback: sweep gmem again

    // ---- level 2: bits [19:10], per-group 1024-bin hist over candidates ----
    if (!ovf) {
        for (int i = tid; i < cnt; i += NTHREADS) {
            unsigned key = list[i];
            int g = gmask[key >> 20];  // >= 1 by construction
            atomicAdd(&hist2[(g - 1) * 1024 + ((key >> 10) & 1023u)], 1u);
        }
    } else {
        for (int i = tid; i < (n + 3) >> 2; i += NTHREADS) {
            float4 v = x4[i];
            const int t0 = i << 2;
            float vv[4] = {v.x, v.y, v.z, v.w};
#pragma unroll
            for (int j = 0; j < 4; ++j) {
                if (t0 + j < n) {
                    unsigned key = f2k(vv[j]);
                    int g = gmask[key >> 20];
                    if (g) atomicAdd(&hist2[(g - 1) * 1024 + ((key >> 10) & 1023u)], 1u);
                }
            }
        }
    }
    __syncthreads();

    // level-2 scan: warp j resolves target j
    if (warp < 6) {
        const unsigned* h = hist2 + s_g12[warp] * 1024;
        unsigned kk = s_krem[warp];
        unsigned ls = 0;
        for (int t = 0; t < 32; ++t) ls += h[lane * 32 + t];
        unsigned inc2 = ls;
#pragma unroll
        for (int o = 1; o < 32; o <<= 1) {
            unsigned u = __shfl_up_sync(FULL, inc2, o);
            if (lane >= o) inc2 += u;
        }
        unsigned exc = inc2 - ls;
        if (kk >= exc && kk < inc2) {
            unsigned cum = exc;
            for (int t = 0; t < 32; ++t) {
                unsigned cb = h[lane * 32 + t];
                if (kk < cum + cb) { s_dig2[warp] = lane * 32 + t; s_krem2[warp] = kk - cum; break; }
                cum += cb;
            }
        }
    }
    __syncthreads();

    // ---- dedup 22-bit prefixes ----
    if (tid == 0) {
        int ng = 0;
#pragma unroll
        for (int j = 0; j < 6; ++j) {
            unsigned p22 = (s_pfx12[j] << 10) | s_dig2[j];
            s_p22[j] = p22;
            int g = -1;
            for (int g2 = 0; g2 < ng; ++g2) if (s_upfx22[g2] == p22) { g = g2; break; }
            if (g < 0) { g = ng; s_upfx22[ng++] = p22; }
            s_g3[j] = g;
        }
        s_ng3 = ng;
    }
    __syncthreads();
    for (int i = tid; i < 6 * 1024; i += NTHREADS) hist2[i] = 0u;
    __syncthreads();

    // ---- level 3: bits [9:0] ----
    const int ng3 = s_ng3;
    if (!ovf) {
        for (int i = tid; i < cnt; i += NTHREADS) {
            unsigned key = list[i];
            unsigned p = key >> 10;
            for (int g = 0; g < ng3; ++g)
                if (p == s_upfx22[g]) { atomicAdd(&hist2[g * 1024 + (key & 1023u)], 1u); break; }
        }
    } else {
        for (int i = tid; i < (n + 3) >> 2; i += NTHREADS) {
            float4 v = x4[i];
            const int t0 = i << 2;
            float vv[4] = {v.x, v.y, v.z, v.w};
#pragma unroll
            for (int j = 0; j < 4; ++j) {
                if (t0 + j < n) {
                    unsigned key = f2k(vv[j]);
                    unsigned p = key >> 10;
                    for (int g = 0; g < ng3; ++g)
                        if (p == s_upfx22[g]) { atomicAdd(&hist2[g * 1024 + (key & 1023u)], 1u); break; }
                }
            }
        }
    }
    __syncthreads();

    if (warp < 6) {
        const unsigned* h = hist2 + s_g3[warp] * 1024;
        unsigned kk = s_krem2[warp];
        unsigned ls = 0;
        for (int t = 0; t < 32; ++t) ls += h[lane * 32 + t];
        unsigned inc3 = ls;
#pragma unroll
        for (int o = 1; o < 32; o <<= 1) {
            unsigned u = __shfl_up_sync(FULL, inc3, o);
            if (lane >= o) inc3 += u;
        }
        unsigned exc = inc3 - ls;
        if (kk >= exc && kk < inc3) {
            unsigned cum = exc;
            for (int t = 0; t < 32; ++t) {
                unsigned cb = h[lane * 32 + t];
                if (kk < cum + cb) { s_keyout[warp] = (s_p22[warp] << 10) | (unsigned)(lane * 32 + t); break; }
                cum += cb;
            }
        }
    }
    __syncthreads();

    if (tid < 3) {
        float vlo = k2f(s_keyout[2 * tid]);
        float vhi = k2f(s_keyout[2 * tid + 1]);
        out[b * (5 * C_DIM) + (2 + tid) * C_DIM + c] = vlo + s_w[tid] * (vhi - vlo);
    }
}

extern "C" void kernel_launch(void* const* d_in, const int* in_sizes, int n_in,
                              void* d_out, int out_size) {
    const float* x;
    const int* lengths;
    if (in_sizes[0] == B_DIM) {
        lengths = (const int*)d_in[0];
        x = (const float*)d_in[1];
    } else {
        x = (const float*)d_in[0];
        lengths = (const int*)d_in[1];
    }
    float* out = (float*)d_out;

    size_t smem = (size_t)(NBIN1 + 6 * 1024) * sizeof(unsigned) + 4096;  // ~44 KB
    cudaFuncSetAttribute(statpool_kernel,
                         cudaFuncAttributeMaxDynamicSharedMemorySize, (int)smem);
    statpool_kernel<<<B_DIM * C_DIM, NTHREADS, smem>>>(x, lengths, out);
}

// round 6
// speedup vs baseline: 3.5919x; 3.5919x over previous
#include <cuda_runtime.h>
#include <math.h>

#define B_DIM 64
#define C_DIM 80
#define T_DIM 16384
#define NTHREADS 512
#define NWARPS 16
#define NBIN 4096
#define CAP_G 680           // per-group candidate capacity (6*680 <= 4096)
#define FULL 0xFFFFFFFFu

// order-preserving float <-> u32 key (for exact total-order selection)
__device__ __forceinline__ unsigned f2k(float f) {
    unsigned u = __float_as_uint(f);
    return u ^ ((unsigned)((int)u >> 31) | 0x80000000u);
}
__device__ __forceinline__ float k2f(unsigned k) {
    unsigned m = (k & 0x80000000u) ? 0x80000000u : 0xFFFFFFFFu;
    return __uint_as_float(k ^ m);
}

// value-linear bin: 4096 bins across [-4, 4]; clamped; deterministic
__device__ __forceinline__ int vbin(float f) {
    int bi = __float2int_rd(fmaf(f, 512.0f, 2048.0f));
    return max(0, min(NBIN - 1, bi));
}

__global__ void __launch_bounds__(NTHREADS, 3)
statpool_kernel(const float* __restrict__ x, const int* __restrict__ lengths,
                float* __restrict__ out) {
    extern __shared__ unsigned sh[];
    unsigned* hist = sh;                         // [4096]; reused as candidate lists
    unsigned char* gmask = (unsigned char*)(sh + NBIN);  // [4096] bin -> group+1

    __shared__ float red_s[NWARPS], red_s2[NWARPS];
    __shared__ unsigned wtot[NWARPS], wbase[NWARPS];
    __shared__ unsigned s_k[6];                  // global target ranks
    __shared__ float s_w[3];
    __shared__ int s_bin[6];                     // bin holding each target
    __shared__ unsigned s_krem[6];               // rank within bin
    __shared__ int s_g[6];                       // group id per target
    __shared__ int s_gcnt[6];                    // per-group candidate counts
    __shared__ unsigned s_keyout[6];

    const int row = blockIdx.x;
    const int b = row / C_DIM, c = row % C_DIM;
    const int n = lengths[b];
    const int tid = threadIdx.x, lane = tid & 31, warp = tid >> 5;

    for (int i = tid; i < NBIN; i += NTHREADS) hist[i] = 0u;
    if (tid < 6) s_gcnt[tid] = 0;
    __syncthreads();

    // ---- pass 1: sum/sumsq + value-linear histogram (low-conflict atomics).
    //      No warp collectives anywhere in this loop. ----
    const float4* x4 = (const float4*)(x + (size_t)row * T_DIM);
    const int nvec = (n + 3) >> 2;
    float sum = 0.f, sumsq = 0.f;
    for (int i = tid; i < nvec; i += NTHREADS) {
        float4 v = x4[i];
        const int t0 = i << 2;
        float vv[4] = {v.x, v.y, v.z, v.w};
#pragma unroll
        for (int j = 0; j < 4; ++j) {
            if (t0 + j < n) {
                float f = vv[j];
                sum += f; sumsq += f * f;
                atomicAdd(&hist[vbin(f)], 1u);
            }
        }
    }

    // ---- block reduce sums (uniform control flow) ----
#pragma unroll
    for (int o = 16; o; o >>= 1) {
        sum += __shfl_down_sync(FULL, sum, o);
        sumsq += __shfl_down_sync(FULL, sumsq, o);
    }
    if (lane == 0) { red_s[warp] = sum; red_s2[warp] = sumsq; }
    __syncthreads();

    // ---- scan hist (inclusive, in place): thread owns 8 consecutive bins ----
    unsigned vb[8], loc = 0;
#pragma unroll
    for (int d = 0; d < 8; ++d) { vb[d] = hist[tid * 8 + d]; loc += vb[d]; }
    unsigned inc = loc;
#pragma unroll
    for (int o = 1; o < 32; o <<= 1) {
        unsigned t = __shfl_up_sync(FULL, inc, o);
        if (lane >= o) inc += t;
    }
    if (lane == 31) wtot[warp] = inc;
    __syncthreads();

    if (warp == 0) {
        unsigned t = (lane < NWARPS) ? wtot[lane] : 0u;
        unsigned ti = t;
#pragma unroll
        for (int o = 1; o < 16; o <<= 1) {
            unsigned u = __shfl_up_sync(FULL, ti, o);
            if (lane >= o) ti += u;
        }
        if (lane < NWARPS) wbase[lane] = ti - t;
    } else if (tid == 32) {
        // mean/std + rank targets (concurrent with warp 0's base scan)
        float s = 0.f, s2 = 0.f;
#pragma unroll
        for (int w = 0; w < NWARPS; ++w) { s += red_s[w]; s2 += red_s2[w]; }
        float fn = (float)n;
        float mean = s / fn;
        float var = fmaxf(s2 / fn - mean * mean, 1e-6f);
        out[b * (5 * C_DIM) + 0 * C_DIM + c] = mean;
        out[b * (5 * C_DIM) + 1 * C_DIM + c] = sqrtf(var);
        float n1 = (float)(n - 1);
        const float qs[3] = {0.25f, 0.5f, 0.75f};
#pragma unroll
        for (int q = 0; q < 3; ++q) {
            float pos = qs[q] * n1;
            float flo = floorf(pos);
            s_k[2 * q]     = (unsigned)(int)flo;
            s_k[2 * q + 1] = (unsigned)(int)ceilf(pos);
            s_w[q] = pos - flo;
        }
    }
    __syncthreads();

    unsigned run = wbase[warp] + (inc - loc);
#pragma unroll
    for (int d = 0; d < 8; ++d) { run += vb[d]; hist[tid * 8 + d] = run; }
    __syncthreads();

    // ---- locate bin per target (6 threads binary search on cumsum);
    //      others zero gmask concurrently ----
    if (tid < 6) {
        unsigned k = s_k[tid];
        int lo = 0, hi = NBIN - 1;
        while (lo < hi) {
            int mid = (lo + hi) >> 1;
            if (hist[mid] > k) hi = mid; else lo = mid + 1;
        }
        s_bin[tid] = lo;
        s_krem[tid] = k - (lo ? hist[lo - 1] : 0u);
    }
    {
        unsigned* gm32 = (unsigned*)gmask;
        for (int i = tid + 6; i < 1024 + 6; i += NTHREADS)
            if (i - 6 < 1024) gm32[i - 6] = 0u;
    }
    __syncthreads();

    // ---- dedup bins into groups, fill gmask ----
    if (tid == 0) {
        int ng = 0;
        int ubin[6];
#pragma unroll
        for (int j = 0; j < 6; ++j) {
            int p = s_bin[j];
            int g = -1;
            for (int g2 = 0; g2 < ng; ++g2) if (ubin[g2] == p) { g = g2; break; }
            if (g < 0) { g = ng; ubin[ng++] = p; gmask[p] = (unsigned char)(g + 1); }
            s_g[j] = g;
        }
    }
    __syncthreads();

    // ---- pass 2: compaction into per-group lists (keys). No collectives. ----
    unsigned* list = hist;  // overlay; cumsum no longer needed
    for (int i = tid; i < nvec; i += NTHREADS) {
        float4 v = x4[i];
        const int t0 = i << 2;
        float vv[4] = {v.x, v.y, v.z, v.w};
#pragma unroll
        for (int j = 0; j < 4; ++j) {
            if (t0 + j < n) {
                float f = vv[j];
                int g = gmask[vbin(f)];
                if (g) {
                    int pos = atomicAdd(&s_gcnt[g - 1], 1);
                    if (pos < CAP_G) list[(g - 1) * CAP_G + pos] = f2k(f);
                }
            }
        }
    }
    __syncthreads();

    // ---- exact selection: warp j resolves target j ----
    if (warp < 6) {
        const int g = s_g[warp];
        const int cnt = s_gcnt[g];
        const unsigned kk = s_krem[warp];

        if (cnt <= CAP_G) {
            // stable-rank brute force over small candidate list
            const unsigned* L = list + g * CAP_G;
            const int m = cnt;
            for (int base = 0; base < m; base += 32) {
                int idx = base + lane;
                unsigned e = (idx < m) ? L[idx] : 0xFFFFFFFFu;
                unsigned cl = 0, ce = 0;
                for (int t = 0; t < m; ++t) {
                    unsigned o = L[t];          // broadcast read
                    cl += (o < e);
                    ce += (o == e && t < idx);
                }
                if (idx < m && cl + ce == kk) s_keyout[warp] = e;
            }
        } else {
            // fallback (adversarial duplicates): exact 32-step key bisection
            // over global row; uniform trip counts, converged reductions.
            const float* xs = (const float*)x4;
            const unsigned kglob = s_k[warp];
            unsigned prefix = 0u;
            for (int bit = 31; bit >= 0; --bit) {
                unsigned cand = prefix | (1u << bit);
                unsigned cnt2 = 0;
                for (int i2 = lane; i2 < T_DIM; i2 += 32) {
                    if (i2 < n) cnt2 += (f2k(xs[i2]) < cand) ? 1u : 0u;
                }
#pragma unroll
                for (int o = 16; o; o >>= 1)
                    cnt2 += __shfl_down_sync(FULL, cnt2, o);
                cnt2 = __shfl_sync(FULL, cnt2, 0);
                if (cnt2 <= kglob) prefix = cand;
            }
            if (lane == 0) s_keyout[warp] = prefix;
        }
    }
    __syncthreads();

    // ---- quantile interpolation + writeback ----
    if (tid < 3) {
        float vlo = k2f(s_keyout[2 * tid]);
        float vhi = k2f(s_keyout[2 * tid + 1]);
        out[b * (5 * C_DIM) + (2 + tid) * C_DIM + c] = vlo + s_w[tid] * (vhi - vlo);
    }
}

extern "C" void kernel_launch(void* const* d_in, const int* in_sizes, int n_in,
                              void* d_out, int out_size) {
    const float* x;
    const int* lengths;
    if (in_sizes[0] == B_DIM) {
        lengths = (const int*)d_in[0];
        x = (const float*)d_in[1];
    } else {
        x = (const float*)d_in[0];
        lengths = (const int*)d_in[1];
    }
    float* out = (float*)d_out;

    size_t smem = (size_t)NBIN * sizeof(unsigned) + NBIN;  // 16 KB + 4 KB
    cudaFuncSetAttribute(statpool_kernel,
                         cudaFuncAttributeMaxDynamicSharedMemorySize, (int)smem);
    statpool_kernel<<<B_DIM * C_DIM, NTHREADS, smem>>>(x, lengths, out);
}